// round 15
// baseline (speedup 1.0000x reference)
#include <cuda_runtime.h>
#include <math.h>

#define MDIM 4096
#define NT 32             // 32 tile-rows of 128
#define TILE 128
#define NCHUNK 272        // sum over ti of ceil((32-ti)/2)
#define B1f 0.9f
#define B2f 0.999f
#define EPSV 1e-8f
#define LRV 0.1f
#define NSTEPS 199

// ---- scratch (__device__ globals; no allocation) ----
__device__ float d_Qs[(size_t)MDIM * MDIM];      // symmetrized fp32 (upper half valid)
__device__ float d_g[(NSTEPS + 1)][MDIM];
__device__ float d_W[2][MDIM];
__device__ float d_MT[2][MDIM];
__device__ float d_VT[2][MDIM];

// ---------------------------------------------------------------------------
__global__ void prep_qs_kernel(const float* __restrict__ va) {
    __shared__ float tile[32][33];
    int bx = blockIdx.x * 32, by = blockIdx.y * 32;
    if (bx + 32 <= by) return;                   // upper-triangle blocks only
    int tx = threadIdx.x, ty = threadIdx.y;
    tile[ty][tx] = va[(size_t)(bx + ty) * MDIM + (by + tx)];
    __syncthreads();
    size_t idx = (size_t)(by + ty) * MDIM + (bx + tx);
    d_Qs[idx] = 0.5f * (va[idx] + tile[tx][ty]);
}

// ---------------------------------------------------------------------------
__global__ void init_kernel() {
    int i = blockIdx.x * blockDim.x + threadIdx.x;
    if (i < MDIM) {
        d_W[0][i] = 1.0f;  d_W[1][i] = 1.0f;
        d_MT[0][i] = 0.0f; d_MT[1][i] = 0.0f;
        d_VT[0][i] = 0.0f; d_VT[1][i] = 0.0f;
    }
    int total = (NSTEPS + 1) * MDIM;
    for (int j = i; j < total; j += gridDim.x * blockDim.x)
        (&d_g[0][0])[j] = 0.0f;
}

// ---------------------------------------------------------------------------
__device__ __forceinline__ void load_batch(float4* dst, const float4* __restrict__ Q4,
                                           size_t qb) {
    #pragma unroll
    for (int i = 0; i < 8; ++i)
        dst[i] = Q4[qb + (size_t)i * (MDIM / 4)];
}

__device__ __forceinline__ void compute_batch(const float4* qv, int roff, bool diagk,
                                              int w, int lane, const float* xsI,
                                              float4 xj, float* rp, float4& ca) {
    if (!diagk) {
        #pragma unroll
        for (int i = 0; i < 8; ++i) {
            float xi = xsI[w * 16 + roff + i];
            rp[roff + i] += qv[i].x * xj.x + qv[i].y * xj.y
                          + qv[i].z * xj.z + qv[i].w * xj.w;
            ca.x = fmaf(qv[i].x, xi, ca.x);
            ca.y = fmaf(qv[i].y, xi, ca.y);
            ca.z = fmaf(qv[i].z, xi, ca.z);
            ca.w = fmaf(qv[i].w, xi, ca.w);
        }
    } else {
        int c0 = 4 * lane;
        #pragma unroll
        for (int i = 0; i < 8; ++i) {
            int r = w * 16 + roff + i;
            float xi = xsI[r];
            float r0 = (c0 + 0 >= r) ? qv[i].x * xj.x : 0.f;
            float r1 = (c0 + 1 >= r) ? qv[i].y * xj.y : 0.f;
            float r2 = (c0 + 2 >= r) ? qv[i].z * xj.z : 0.f;
            float r3 = (c0 + 3 >= r) ? qv[i].w * xj.w : 0.f;
            rp[roff + i] += (r0 + r1) + (r2 + r3);
            if (c0 + 0 > r) ca.x = fmaf(qv[i].x, xi, ca.x);
            if (c0 + 1 > r) ca.y = fmaf(qv[i].y, xi, ca.y);
            if (c0 + 2 > r) ca.z = fmaf(qv[i].z, xi, ca.z);
            if (c0 + 3 > r) ca.w = fmaf(qv[i].w, xi, ca.w);
        }
    }
}

// per-lane column flush: 4 distinct global addresses, fire-and-forget
__device__ __forceinline__ void flush_cols(float* __restrict__ g_out, int J,
                                           int lane, const float4& ca) {
    atomicAdd(&g_out[J + 4 * lane + 0], ca.x);
    atomicAdd(&g_out[J + 4 * lane + 1], ca.y);
    atomicAdd(&g_out[J + 4 * lane + 2], ca.z);
    atomicAdd(&g_out[J + 4 * lane + 3], ca.w);
}

// ---------------------------------------------------------------------------
// One launch per step, PDL-overlapped with EARLY trigger. Block = up to 2
// tiles in one tile-row. Column partials flushed inline (off the tail).
// ---------------------------------------------------------------------------
__global__ __launch_bounds__(256, 2)
void adam_symv_kernel(const float* __restrict__ mean,
                      const float* __restrict__ g_prev,
                      float* __restrict__ g_out,
                      int p, float step_lr, float inv_sqrt_bc2)
{
    __shared__ float xsI[TILE];
    __shared__ float xsJ[2][TILE];
    __shared__ float part[TILE][33];

    // block -> (ti, pair-chunk)
    int b = blockIdx.x;
    int ti = 0;
    for (;;) {
        int chunks = (NT - ti + 1) >> 1;
        if (b < chunks) break;
        b -= chunks; ++ti;
    }
    int tj0 = ti + 2 * b;
    int nt  = NT - tj0; if (nt > 2) nt = 2;
    const int I = ti * TILE;
    const bool diag = (tj0 == ti);     // only tile0 can be diagonal

    int tid = threadIdx.x, w = tid >> 5, lane = tid & 31;
    int q = p ^ 1;
    const float4* __restrict__ Q4 = reinterpret_cast<const float4*>(d_Qs);
    size_t rowbase = (size_t)(I + w * 16) * (MDIM / 4) + lane;

    // earliest trigger: let the NEXT step's grid start launching now.
    cudaTriggerProgrammaticLaunchCompletion();

    // pre-sync preamble: prefetch tile0 batches A+B (step-invariant data)
    float4 qv[8], qn[8];
    load_batch(qv, Q4, rowbase + (size_t)tj0 * 32);
    load_batch(qn, Q4, rowbase + (size_t)tj0 * 32 + 8 * (MDIM / 4));

    // wait for upstream step's memory to be visible (no-op if PDL inactive)
    cudaGridDependencySynchronize();

    // ---- prologue: Adam step for band I + non-diag J bands; build x ----
    for (int idx = tid; idx < (1 + nt) * TILE; idx += 256) {
        int band = idx >> 7;
        int r    = idx & 127;
        int grow;
        if (band == 0) grow = I + r;
        else {
            int tj = tj0 + band - 1;
            if (tj == ti) continue;
            grow = tj * TILE + r;
        }
        float g  = g_prev[grow];
        float mt = B1f * d_MT[p][grow] + (1.0f - B1f) * g;
        float vt = B2f * d_VT[p][grow] + (1.0f - B2f) * g * g;
        float wn = d_W[p][grow]
                 - __fdividef(step_lr * mt, sqrtf(vt) * inv_sqrt_bc2 + EPSV);
        d_W[q][grow]  = wn;
        d_MT[q][grow] = mt;
        d_VT[q][grow] = vt;
        float x = wn - mean[grow];
        if (band == 0) {
            xsI[r] = x;
            if (diag) xsJ[0][r] = x;
        } else {
            xsJ[band - 1][r] = x;
        }
    }
    __syncthreads();

    // ---- main: double-buffered 8-row batches across up to 2 tiles ----
    float rp[16] = {0.f,0.f,0.f,0.f,0.f,0.f,0.f,0.f,
                    0.f,0.f,0.f,0.f,0.f,0.f,0.f,0.f};

    float4 xj0 = reinterpret_cast<const float4*>(xsJ[0])[lane];
    float4 ca0 = make_float4(0.f, 0.f, 0.f, 0.f);

    compute_batch(qv, 0, diag, w, lane, xsI, xj0, rp, ca0);             // tile0 A

    if (nt == 2) {
        load_batch(qv, Q4, rowbase + (size_t)(tj0 + 1) * 32);           // tile1 A
        compute_batch(qn, 8, diag, w, lane, xsI, xj0, rp, ca0);         // tile0 B
        flush_cols(g_out, tj0 * TILE, lane, ca0);                       // inline flush

        float4 xj1 = reinterpret_cast<const float4*>(xsJ[1])[lane];
        float4 ca1 = make_float4(0.f, 0.f, 0.f, 0.f);
        load_batch(qn, Q4, rowbase + (size_t)(tj0 + 1) * 32 + 8 * (MDIM / 4)); // tile1 B
        compute_batch(qv, 0, false, w, lane, xsI, xj1, rp, ca1);        // tile1 A
        compute_batch(qn, 8, false, w, lane, xsI, xj1, rp, ca1);        // tile1 B
        flush_cols(g_out, (tj0 + 1) * TILE, lane, ca1);                 // inline flush
    } else {
        compute_batch(qn, 8, diag, w, lane, xsI, xj0, rp, ca0);         // tile0 B
        flush_cols(g_out, tj0 * TILE, lane, ca0);                       // inline flush
    }

    // ---- short tail: row partial dump + reduce + flush ----
    #pragma unroll
    for (int k = 0; k < 16; ++k)
        part[w * 16 + k][lane] = rp[k];
    __syncthreads();

    if (tid < TILE) {
        float acc = 0.f;
        #pragma unroll
        for (int l = 0; l < 32; ++l) acc += part[tid][l];
        atomicAdd(&g_out[I + tid], acc);
    }
}

// ---------------------------------------------------------------------------
__global__ void finish_kernel(float* __restrict__ out,
                              const float* __restrict__ g_last,
                              int p, float step_lr, float inv_sqrt_bc2) {
    cudaGridDependencySynchronize();
    int i = blockIdx.x * blockDim.x + threadIdx.x;
    if (i < MDIM) {
        float g  = g_last[i];
        float mt = B1f * d_MT[p][i] + (1.0f - B1f) * g;
        float vt = B2f * d_VT[p][i] + (1.0f - B2f) * g * g;
        out[i] = d_W[p][i] - step_lr * mt / (sqrtf(vt) * inv_sqrt_bc2 + EPSV);
    }
}

// ---------------------------------------------------------------------------
extern "C" void kernel_launch(void* const* d_in, const int* in_sizes, int n_in,
                              void* d_out, int out_size) {
    const float* mean = (const float*)d_in[0];
    const float* va   = (const float*)d_in[1];
    float* out = (float*)d_out;
    (void)in_sizes; (void)n_in; (void)out_size;

    float* g_base; cudaGetSymbolAddress((void**)&g_base, d_g);

    dim3 tb(32, 32), tg(MDIM / 32, MDIM / 32);
    prep_qs_kernel<<<tg, tb>>>(va);
    init_kernel<<<128, 256>>>();

    cudaLaunchAttribute attrs[1];
    attrs[0].id = cudaLaunchAttributeProgrammaticStreamSerialization;
    attrs[0].val.programmaticStreamSerializationAllowed = 1;

    for (int s = 1; s <= NSTEPS; ++s) {
        int t = s - 1;
        float step_lr = 0.f, inv_b2 = 0.f;
        if (t >= 1) {
            double bc1 = 1.0 - pow(0.9,   (double)t);
            double bc2 = 1.0 - pow(0.999, (double)t);
            step_lr = (float)((double)LRV / bc1);
            inv_b2  = (float)(1.0 / sqrt(bc2));
        }
        int p = (s - 1) & 1;

        cudaLaunchConfig_t cfg = {};
        cfg.gridDim  = dim3(NCHUNK, 1, 1);
        cfg.blockDim = dim3(256, 1, 1);
        cfg.attrs    = attrs;
        cfg.numAttrs = 1;
        cudaLaunchKernelEx(&cfg, adam_symv_kernel, mean,
                           (const float*)(g_base + (size_t)(s - 1) * MDIM),
                           (float*)(g_base + (size_t)s * MDIM),
                           p, step_lr, inv_b2);
    }

    {
        int t = NSTEPS;
        double bc1 = 1.0 - pow(0.9,   (double)t);
        double bc2 = 1.0 - pow(0.999, (double)t);
        float step_lr = (float)((double)LRV / bc1);
        float inv_b2  = (float)(1.0 / sqrt(bc2));

        cudaLaunchConfig_t cfg = {};
        cfg.gridDim  = dim3((MDIM + 255) / 256, 1, 1);
        cfg.blockDim = dim3(256, 1, 1);
        cfg.attrs    = attrs;
        cfg.numAttrs = 1;
        cudaLaunchKernelEx(&cfg, finish_kernel, out,
                           (const float*)(g_base + (size_t)NSTEPS * MDIM),
                           (int)(NSTEPS & 1), step_lr, inv_b2);
    }
}

// round 16
// speedup vs baseline: 3.0762x; 3.0762x over previous
#include <cuda_runtime.h>
#include <math.h>

#define MDIM 4096
#define NT 32             // 32 tile-rows of 128
#define TILE 128
#define NCHUNK 272        // sum over ti of ceil((32-ti)/2)
#define B1f 0.9f
#define B2f 0.999f
#define EPSV 1e-8f
#define LRV 0.1f
#define NSTEPS 199

// ---- scratch (__device__ globals; no allocation) ----
__device__ float d_Qs[(size_t)MDIM * MDIM];      // symmetrized fp32 (upper half valid)
__device__ float d_g[(NSTEPS + 1)][MDIM];
__device__ float d_W[2][MDIM];
__device__ float d_MT[2][MDIM];
__device__ float d_VT[2][MDIM];

// ---------------------------------------------------------------------------
__global__ void prep_qs_kernel(const float* __restrict__ va) {
    __shared__ float tile[32][33];
    int bx = blockIdx.x * 32, by = blockIdx.y * 32;
    if (bx + 32 <= by) return;                   // upper-triangle blocks only
    int tx = threadIdx.x, ty = threadIdx.y;
    tile[ty][tx] = va[(size_t)(bx + ty) * MDIM + (by + tx)];
    __syncthreads();
    size_t idx = (size_t)(by + ty) * MDIM + (bx + tx);
    d_Qs[idx] = 0.5f * (va[idx] + tile[tx][ty]);
}

// ---------------------------------------------------------------------------
__global__ void init_kernel() {
    int i = blockIdx.x * blockDim.x + threadIdx.x;
    if (i < MDIM) {
        d_W[0][i] = 1.0f;  d_W[1][i] = 1.0f;
        d_MT[0][i] = 0.0f; d_MT[1][i] = 0.0f;
        d_VT[0][i] = 0.0f; d_VT[1][i] = 0.0f;
    }
    int total = (NSTEPS + 1) * MDIM;
    for (int j = i; j < total; j += gridDim.x * blockDim.x)
        (&d_g[0][0])[j] = 0.0f;
}

// ---------------------------------------------------------------------------
__device__ __forceinline__ void load_batch(float4* dst, const float4* __restrict__ Q4,
                                           size_t qb) {
    #pragma unroll
    for (int i = 0; i < 8; ++i)
        dst[i] = Q4[qb + (size_t)i * (MDIM / 4)];
}

__device__ __forceinline__ void compute_batch(const float4* qv, int roff, bool diagk,
                                              int w, int lane, const float* xsI,
                                              float4 xj, float* rp, float4& ca) {
    if (!diagk) {
        #pragma unroll
        for (int i = 0; i < 8; ++i) {
            float xi = xsI[w * 16 + roff + i];
            rp[roff + i] += qv[i].x * xj.x + qv[i].y * xj.y
                          + qv[i].z * xj.z + qv[i].w * xj.w;
            ca.x = fmaf(qv[i].x, xi, ca.x);
            ca.y = fmaf(qv[i].y, xi, ca.y);
            ca.z = fmaf(qv[i].z, xi, ca.z);
            ca.w = fmaf(qv[i].w, xi, ca.w);
        }
    } else {
        int c0 = 4 * lane;
        #pragma unroll
        for (int i = 0; i < 8; ++i) {
            int r = w * 16 + roff + i;
            float xi = xsI[r];
            float r0 = (c0 + 0 >= r) ? qv[i].x * xj.x : 0.f;
            float r1 = (c0 + 1 >= r) ? qv[i].y * xj.y : 0.f;
            float r2 = (c0 + 2 >= r) ? qv[i].z * xj.z : 0.f;
            float r3 = (c0 + 3 >= r) ? qv[i].w * xj.w : 0.f;
            rp[roff + i] += (r0 + r1) + (r2 + r3);
            if (c0 + 0 > r) ca.x = fmaf(qv[i].x, xi, ca.x);
            if (c0 + 1 > r) ca.y = fmaf(qv[i].y, xi, ca.y);
            if (c0 + 2 > r) ca.z = fmaf(qv[i].z, xi, ca.z);
            if (c0 + 3 > r) ca.w = fmaf(qv[i].w, xi, ca.w);
        }
    }
}

// ---------------------------------------------------------------------------
// One launch per step, PDL-overlapped with EARLY trigger. Block = up to 2
// tiles in one tile-row. Pre-sync preamble touches ONLY step-invariant d_Qs.
// ---------------------------------------------------------------------------
__global__ __launch_bounds__(256, 2)
void adam_symv_kernel(const float* __restrict__ mean,
                      const float* __restrict__ g_prev,
                      float* __restrict__ g_out,
                      int p, float step_lr, float inv_sqrt_bc2)
{
    __shared__ float xsI[TILE];
    __shared__ float xsJ[2][TILE];
    __shared__ float part[TILE][33];
    __shared__ float colp[2][8][TILE];

    // block -> (ti, pair-chunk)
    int b = blockIdx.x;
    int ti = 0;
    for (;;) {
        int chunks = (NT - ti + 1) >> 1;
        if (b < chunks) break;
        b -= chunks; ++ti;
    }
    int tj0 = ti + 2 * b;
    int nt  = NT - tj0; if (nt > 2) nt = 2;
    const int I = ti * TILE;
    const bool diag = (tj0 == ti);     // only tile0 can be diagonal

    int tid = threadIdx.x, w = tid >> 5, lane = tid & 31;
    int q = p ^ 1;
    const float4* __restrict__ Q4 = reinterpret_cast<const float4*>(d_Qs);
    size_t rowbase = (size_t)(I + w * 16) * (MDIM / 4) + lane;

    // earliest trigger: let the NEXT step's grid start launching now.
    cudaTriggerProgrammaticLaunchCompletion();

    // pre-sync preamble: prefetch tile0 batches A+B (step-invariant data)
    float4 qv[8], qn[8];
    load_batch(qv, Q4, rowbase + (size_t)tj0 * 32);
    load_batch(qn, Q4, rowbase + (size_t)tj0 * 32 + 8 * (MDIM / 4));

    // wait for upstream step's memory to be visible (no-op if PDL inactive)
    cudaGridDependencySynchronize();

    // ---- prologue: Adam step for band I + non-diag J bands; build x ----
    for (int idx = tid; idx < (1 + nt) * TILE; idx += 256) {
        int band = idx >> 7;
        int r    = idx & 127;
        int grow;
        if (band == 0) grow = I + r;
        else {
            int tj = tj0 + band - 1;
            if (tj == ti) continue;
            grow = tj * TILE + r;
        }
        float g  = g_prev[grow];
        float mt = B1f * d_MT[p][grow] + (1.0f - B1f) * g;
        float vt = B2f * d_VT[p][grow] + (1.0f - B2f) * g * g;
        float wn = d_W[p][grow]
                 - __fdividef(step_lr * mt, sqrtf(vt) * inv_sqrt_bc2 + EPSV);
        d_W[q][grow]  = wn;
        d_MT[q][grow] = mt;
        d_VT[q][grow] = vt;
        float x = wn - mean[grow];
        if (band == 0) {
            xsI[r] = x;
            if (diag) xsJ[0][r] = x;
        } else {
            xsJ[band - 1][r] = x;
        }
    }
    __syncthreads();

    // ---- main: double-buffered 8-row batches across up to 2 tiles ----
    float rp[16] = {0.f,0.f,0.f,0.f,0.f,0.f,0.f,0.f,
                    0.f,0.f,0.f,0.f,0.f,0.f,0.f,0.f};

    float4 xj0 = reinterpret_cast<const float4*>(xsJ[0])[lane];
    float4 ca0 = make_float4(0.f, 0.f, 0.f, 0.f);

    compute_batch(qv, 0, diag, w, lane, xsI, xj0, rp, ca0);             // tile0 A

    if (nt == 2) {
        load_batch(qv, Q4, rowbase + (size_t)(tj0 + 1) * 32);           // tile1 A
        compute_batch(qn, 8, diag, w, lane, xsI, xj0, rp, ca0);         // tile0 B
        reinterpret_cast<float4*>(colp[0][w])[lane] = ca0;

        float4 xj1 = reinterpret_cast<const float4*>(xsJ[1])[lane];
        float4 ca1 = make_float4(0.f, 0.f, 0.f, 0.f);
        load_batch(qn, Q4, rowbase + (size_t)(tj0 + 1) * 32 + 8 * (MDIM / 4)); // tile1 B
        compute_batch(qv, 0, false, w, lane, xsI, xj1, rp, ca1);        // tile1 A
        compute_batch(qn, 8, false, w, lane, xsI, xj1, rp, ca1);        // tile1 B
        reinterpret_cast<float4*>(colp[1][w])[lane] = ca1;
    } else {
        compute_batch(qn, 8, diag, w, lane, xsI, xj0, rp, ca0);         // tile0 B
        reinterpret_cast<float4*>(colp[0][w])[lane] = ca0;
    }

    // ---- row partial dump + balanced reduce + flush ----
    #pragma unroll
    for (int k = 0; k < 16; ++k)
        part[w * 16 + k][lane] = rp[k];
    __syncthreads();

    if (tid < TILE) {
        // rows only (32 adds)
        float acc = 0.f;
        #pragma unroll
        for (int l = 0; l < 32; ++l) acc += part[tid][l];
        atomicAdd(&g_out[I + tid], acc);
    } else {
        // both column flushes (8 + 8 adds)
        int c = tid - TILE;
        float acc0 = 0.f;
        #pragma unroll
        for (int ww = 0; ww < 8; ++ww) acc0 += colp[0][ww][c];
        atomicAdd(&g_out[tj0 * TILE + c], acc0);
        if (nt == 2) {
            float acc1 = 0.f;
            #pragma unroll
            for (int ww = 0; ww < 8; ++ww) acc1 += colp[1][ww][c];
            atomicAdd(&g_out[(tj0 + 1) * TILE + c], acc1);
        }
    }
}

// ---------------------------------------------------------------------------
__global__ void finish_kernel(float* __restrict__ out,
                              const float* __restrict__ g_last,
                              int p, float step_lr, float inv_sqrt_bc2) {
    cudaGridDependencySynchronize();
    int i = blockIdx.x * blockDim.x + threadIdx.x;
    if (i < MDIM) {
        float g  = g_last[i];
        float mt = B1f * d_MT[p][i] + (1.0f - B1f) * g;
        float vt = B2f * d_VT[p][i] + (1.0f - B2f) * g * g;
        out[i] = d_W[p][i] - step_lr * mt / (sqrtf(vt) * inv_sqrt_bc2 + EPSV);
    }
}

// ---------------------------------------------------------------------------
extern "C" void kernel_launch(void* const* d_in, const int* in_sizes, int n_in,
                              void* d_out, int out_size) {
    const float* mean = (const float*)d_in[0];
    const float* va   = (const float*)d_in[1];
    float* out = (float*)d_out;
    (void)in_sizes; (void)n_in; (void)out_size;

    float* g_base; cudaGetSymbolAddress((void**)&g_base, d_g);

    dim3 tb(32, 32), tg(MDIM / 32, MDIM / 32);
    prep_qs_kernel<<<tg, tb>>>(va);
    init_kernel<<<128, 256>>>();

    cudaLaunchAttribute attrs[1];
    attrs[0].id = cudaLaunchAttributeProgrammaticStreamSerialization;
    attrs[0].val.programmaticStreamSerializationAllowed = 1;

    for (int s = 1; s <= NSTEPS; ++s) {
        int t = s - 1;
        float step_lr = 0.f, inv_b2 = 0.f;
        if (t >= 1) {
            double bc1 = 1.0 - pow(0.9,   (double)t);
            double bc2 = 1.0 - pow(0.999, (double)t);
            step_lr = (float)((double)LRV / bc1);
            inv_b2  = (float)(1.0 / sqrt(bc2));
        }
        int p = (s - 1) & 1;

        cudaLaunchConfig_t cfg = {};
        cfg.gridDim  = dim3(NCHUNK, 1, 1);
        cfg.blockDim = dim3(256, 1, 1);
        cfg.attrs    = attrs;
        cfg.numAttrs = 1;
        cudaLaunchKernelEx(&cfg, adam_symv_kernel, mean,
                           (const float*)(g_base + (size_t)(s - 1) * MDIM),
                           (float*)(g_base + (size_t)s * MDIM),
                           p, step_lr, inv_b2);
    }

    {
        int t = NSTEPS;
        double bc1 = 1.0 - pow(0.9,   (double)t);
        double bc2 = 1.0 - pow(0.999, (double)t);
        float step_lr = (float)((double)LRV / bc1);
        float inv_b2  = (float)(1.0 / sqrt(bc2));

        cudaLaunchConfig_t cfg = {};
        cfg.gridDim  = dim3((MDIM + 255) / 256, 1, 1);
        cfg.blockDim = dim3(256, 1, 1);
        cfg.attrs    = attrs;
        cfg.numAttrs = 1;
        cudaLaunchKernelEx(&cfg, finish_kernel, out,
                           (const float*)(g_base + (size_t)NSTEPS * MDIM),
                           (int)(NSTEPS & 1), step_lr, inv_b2);
    }
}

// round 17
// speedup vs baseline: 3.1141x; 1.0123x over previous
#include <cuda_runtime.h>
#include <math.h>

#define MDIM 4096
#define NT 32             // 32 tile-rows of 128
#define TILE 128
#define NCHUNK 272        // sum over ti of ceil((32-ti)/2)
#define B1f 0.9f
#define B2f 0.999f
#define EPSV 1e-8f
#define LRV 0.1f
#define NSTEPS 199

// ---- scratch (__device__ globals; no allocation) ----
__device__ float d_Qs[(size_t)MDIM * MDIM];      // symmetrized fp32 (upper half valid)
__device__ float d_g[(NSTEPS + 1)][MDIM];
__device__ float4 d_state[2][MDIM];              // packed (W, MT, VT, 0)

// ---------------------------------------------------------------------------
__global__ void prep_qs_kernel(const float* __restrict__ va) {
    __shared__ float tile[32][33];
    int bx = blockIdx.x * 32, by = blockIdx.y * 32;
    if (bx + 32 <= by) return;                   // upper-triangle blocks only
    int tx = threadIdx.x, ty = threadIdx.y;
    tile[ty][tx] = va[(size_t)(bx + ty) * MDIM + (by + tx)];
    __syncthreads();
    size_t idx = (size_t)(by + ty) * MDIM + (bx + tx);
    d_Qs[idx] = 0.5f * (va[idx] + tile[tx][ty]);
}

// ---------------------------------------------------------------------------
__global__ void init_kernel() {
    int i = blockIdx.x * blockDim.x + threadIdx.x;
    if (i < MDIM) {
        d_state[0][i] = make_float4(1.0f, 0.0f, 0.0f, 0.0f);
        d_state[1][i] = make_float4(1.0f, 0.0f, 0.0f, 0.0f);
    }
    int total = (NSTEPS + 1) * MDIM;
    for (int j = i; j < total; j += gridDim.x * blockDim.x)
        (&d_g[0][0])[j] = 0.0f;
}

// ---------------------------------------------------------------------------
__device__ __forceinline__ void load_batch(float4* dst, const float4* __restrict__ Q4,
                                           size_t qb) {
    #pragma unroll
    for (int i = 0; i < 8; ++i)
        dst[i] = Q4[qb + (size_t)i * (MDIM / 4)];
}

__device__ __forceinline__ void compute_batch(const float4* qv, int roff, bool diagk,
                                              int w, int lane, const float* xsI,
                                              float4 xj, float* rp, float4& ca) {
    if (!diagk) {
        #pragma unroll
        for (int i = 0; i < 8; ++i) {
            float xi = xsI[w * 16 + roff + i];
            rp[roff + i] += qv[i].x * xj.x + qv[i].y * xj.y
                          + qv[i].z * xj.z + qv[i].w * xj.w;
            ca.x = fmaf(qv[i].x, xi, ca.x);
            ca.y = fmaf(qv[i].y, xi, ca.y);
            ca.z = fmaf(qv[i].z, xi, ca.z);
            ca.w = fmaf(qv[i].w, xi, ca.w);
        }
    } else {
        int c0 = 4 * lane;
        #pragma unroll
        for (int i = 0; i < 8; ++i) {
            int r = w * 16 + roff + i;
            float xi = xsI[r];
            float r0 = (c0 + 0 >= r) ? qv[i].x * xj.x : 0.f;
            float r1 = (c0 + 1 >= r) ? qv[i].y * xj.y : 0.f;
            float r2 = (c0 + 2 >= r) ? qv[i].z * xj.z : 0.f;
            float r3 = (c0 + 3 >= r) ? qv[i].w * xj.w : 0.f;
            rp[roff + i] += (r0 + r1) + (r2 + r3);
            if (c0 + 0 > r) ca.x = fmaf(qv[i].x, xi, ca.x);
            if (c0 + 1 > r) ca.y = fmaf(qv[i].y, xi, ca.y);
            if (c0 + 2 > r) ca.z = fmaf(qv[i].z, xi, ca.z);
            if (c0 + 3 > r) ca.w = fmaf(qv[i].w, xi, ca.w);
        }
    }
}

// ---------------------------------------------------------------------------
// One launch per step, PDL-overlapped with EARLY trigger. Block = up to 2
// tiles in one tile-row. Pre-sync preamble touches ONLY step-invariant d_Qs.
// ---------------------------------------------------------------------------
__global__ __launch_bounds__(256, 2)
void adam_symv_kernel(const float* __restrict__ mean,
                      const float* __restrict__ g_prev,
                      float* __restrict__ g_out,
                      int p, float step_lr, float inv_sqrt_bc2)
{
    __shared__ float xsI[TILE];
    __shared__ float xsJ[2][TILE];
    __shared__ float part[TILE][33];
    __shared__ float colp[2][8][TILE];

    // block -> (ti, pair-chunk)
    int b = blockIdx.x;
    int ti = 0;
    for (;;) {
        int chunks = (NT - ti + 1) >> 1;
        if (b < chunks) break;
        b -= chunks; ++ti;
    }
    int tj0 = ti + 2 * b;
    int nt  = NT - tj0; if (nt > 2) nt = 2;
    const int I = ti * TILE;
    const bool diag = (tj0 == ti);     // only tile0 can be diagonal

    int tid = threadIdx.x, w = tid >> 5, lane = tid & 31;
    int q = p ^ 1;
    const float4* __restrict__ Q4 = reinterpret_cast<const float4*>(d_Qs);
    size_t rowbase = (size_t)(I + w * 16) * (MDIM / 4) + lane;

    // earliest trigger: let the NEXT step's grid start launching now.
    cudaTriggerProgrammaticLaunchCompletion();

    // pre-sync preamble: prefetch tile0 batches A+B (step-invariant data)
    float4 qv[8], qn[8];
    load_batch(qv, Q4, rowbase + (size_t)tj0 * 32);
    load_batch(qn, Q4, rowbase + (size_t)tj0 * 32 + 8 * (MDIM / 4));

    // wait for upstream step's memory to be visible (no-op if PDL inactive)
    cudaGridDependencySynchronize();

    // ---- prologue: Adam step for band I + non-diag J bands; build x ----
    for (int idx = tid; idx < (1 + nt) * TILE; idx += 256) {
        int band = idx >> 7;
        int r    = idx & 127;
        int grow;
        if (band == 0) grow = I + r;
        else {
            int tj = tj0 + band - 1;
            if (tj == ti) continue;
            grow = tj * TILE + r;
        }
        float  g  = g_prev[grow];
        float4 st = d_state[p][grow];            // (W, MT, VT, -)
        float mt = B1f * st.y + (1.0f - B1f) * g;
        float vt = B2f * st.z + (1.0f - B2f) * g * g;
        float wn = st.x
                 - __fdividef(step_lr * mt, sqrtf(vt) * inv_sqrt_bc2 + EPSV);
        d_state[q][grow] = make_float4(wn, mt, vt, 0.0f);
        float x = wn - mean[grow];
        if (band == 0) {
            xsI[r] = x;
            if (diag) xsJ[0][r] = x;
        } else {
            xsJ[band - 1][r] = x;
        }
    }
    __syncthreads();

    // ---- main: double-buffered 8-row batches across up to 2 tiles ----
    float rp[16] = {0.f,0.f,0.f,0.f,0.f,0.f,0.f,0.f,
                    0.f,0.f,0.f,0.f,0.f,0.f,0.f,0.f};

    float4 xj0 = reinterpret_cast<const float4*>(xsJ[0])[lane];
    float4 ca0 = make_float4(0.f, 0.f, 0.f, 0.f);

    compute_batch(qv, 0, diag, w, lane, xsI, xj0, rp, ca0);             // tile0 A

    if (nt == 2) {
        load_batch(qv, Q4, rowbase + (size_t)(tj0 + 1) * 32);           // tile1 A
        compute_batch(qn, 8, diag, w, lane, xsI, xj0, rp, ca0);         // tile0 B
        reinterpret_cast<float4*>(colp[0][w])[lane] = ca0;

        float4 xj1 = reinterpret_cast<const float4*>(xsJ[1])[lane];
        float4 ca1 = make_float4(0.f, 0.f, 0.f, 0.f);
        load_batch(qn, Q4, rowbase + (size_t)(tj0 + 1) * 32 + 8 * (MDIM / 4)); // tile1 B
        compute_batch(qv, 0, false, w, lane, xsI, xj1, rp, ca1);        // tile1 A
        compute_batch(qn, 8, false, w, lane, xsI, xj1, rp, ca1);        // tile1 B
        reinterpret_cast<float4*>(colp[1][w])[lane] = ca1;
    } else {
        compute_batch(qn, 8, diag, w, lane, xsI, xj0, rp, ca0);         // tile0 B
        reinterpret_cast<float4*>(colp[0][w])[lane] = ca0;
    }

    // ---- row partial dump + balanced reduce + flush ----
    #pragma unroll
    for (int k = 0; k < 16; ++k)
        part[w * 16 + k][lane] = rp[k];
    __syncthreads();

    if (tid < TILE) {
        // rows only (32 adds)
        float acc = 0.f;
        #pragma unroll
        for (int l = 0; l < 32; ++l) acc += part[tid][l];
        atomicAdd(&g_out[I + tid], acc);
    } else {
        // both column flushes (8 + 8 adds)
        int c = tid - TILE;
        float acc0 = 0.f;
        #pragma unroll
        for (int ww = 0; ww < 8; ++ww) acc0 += colp[0][ww][c];
        atomicAdd(&g_out[tj0 * TILE + c], acc0);
        if (nt == 2) {
            float acc1 = 0.f;
            #pragma unroll
            for (int ww = 0; ww < 8; ++ww) acc1 += colp[1][ww][c];
            atomicAdd(&g_out[(tj0 + 1) * TILE + c], acc1);
        }
    }
}

// ---------------------------------------------------------------------------
__global__ void finish_kernel(float* __restrict__ out,
                              const float* __restrict__ g_last,
                              int p, float step_lr, float inv_sqrt_bc2) {
    cudaGridDependencySynchronize();
    int i = blockIdx.x * blockDim.x + threadIdx.x;
    if (i < MDIM) {
        float  g  = g_last[i];
        float4 st = d_state[p][i];
        float mt = B1f * st.y + (1.0f - B1f) * g;
        float vt = B2f * st.z + (1.0f - B2f) * g * g;
        out[i] = st.x - step_lr * mt / (sqrtf(vt) * inv_sqrt_bc2 + EPSV);
    }
}

// ---------------------------------------------------------------------------
extern "C" void kernel_launch(void* const* d_in, const int* in_sizes, int n_in,
                              void* d_out, int out_size) {
    const float* mean = (const float*)d_in[0];
    const float* va   = (const float*)d_in[1];
    float* out = (float*)d_out;
    (void)in_sizes; (void)n_in; (void)out_size;

    float* g_base; cudaGetSymbolAddress((void**)&g_base, d_g);

    dim3 tb(32, 32), tg(MDIM / 32, MDIM / 32);
    prep_qs_kernel<<<tg, tb>>>(va);
    init_kernel<<<128, 256>>>();

    cudaLaunchAttribute attrs[1];
    attrs[0].id = cudaLaunchAttributeProgrammaticStreamSerialization;
    attrs[0].val.programmaticStreamSerializationAllowed = 1;

    for (int s = 1; s <= NSTEPS; ++s) {
        int t = s - 1;
        float step_lr = 0.f, inv_b2 = 0.f;
        if (t >= 1) {
            double bc1 = 1.0 - pow(0.9,   (double)t);
            double bc2 = 1.0 - pow(0.999, (double)t);
            step_lr = (float)((double)LRV / bc1);
            inv_b2  = (float)(1.0 / sqrt(bc2));
        }
        int p = (s - 1) & 1;

        cudaLaunchConfig_t cfg = {};
        cfg.gridDim  = dim3(NCHUNK, 1, 1);
        cfg.blockDim = dim3(256, 1, 1);
        cfg.attrs    = attrs;
        cfg.numAttrs = 1;
        cudaLaunchKernelEx(&cfg, adam_symv_kernel, mean,
                           (const float*)(g_base + (size_t)(s - 1) * MDIM),
                           (float*)(g_base + (size_t)s * MDIM),
                           p, step_lr, inv_b2);
    }

    {
        int t = NSTEPS;
        double bc1 = 1.0 - pow(0.9,   (double)t);
        double bc2 = 1.0 - pow(0.999, (double)t);
        float step_lr = (float)((double)LRV / bc1);
        float inv_b2  = (float)(1.0 / sqrt(bc2));

        cudaLaunchConfig_t cfg = {};
        cfg.gridDim  = dim3((MDIM + 255) / 256, 1, 1);
        cfg.blockDim = dim3(256, 1, 1);
        cfg.attrs    = attrs;
        cfg.numAttrs = 1;
        cudaLaunchKernelEx(&cfg, finish_kernel, out,
                           (const float*)(g_base + (size_t)NSTEPS * MDIM),
                           (int)(NSTEPS & 1), step_lr, inv_b2);
    }
}